// round 17
// baseline (speedup 1.0000x reference)
#include <cuda_runtime.h>
#include <cuda_bf16.h>
#include <cstdint>

#define N_TOK 12288
#define DHEAD 128
#define NUMB  32
#define BM 128
#define BN 64
#define KSPLIT 128
#define MAXPARTS 6
#define NTHREADS 512
#define NWORKERS 148

// dynamic smem byte offsets (160KB, 1 CTA/SM)
#define QH_O 0
#define Q_GAP 32768
#define KH_O 65536
#define VH_O 98304
#define KV_GAP 16384
#define PH_O 131072
#define P_GAP 16384
#define SMEMB 163840

__device__ int   g_seg_start[NUMB + 1];
__device__ int   g_ctr = 0;
__device__ float g_pO[MAXPARTS][N_TOK][DHEAD];
__device__ float g_pl[MAXPARTS][N_TOK];

// ---------------------------------------------------------------------------
// helpers
// ---------------------------------------------------------------------------
__device__ __forceinline__ uint32_t packhl(float a, float b, uint32_t& lo) {
    __nv_bfloat16 ha = __float2bfloat16(a), hb = __float2bfloat16(b);
    __nv_bfloat16 la = __float2bfloat16(a - __bfloat162float(ha));
    __nv_bfloat16 lb = __float2bfloat16(b - __bfloat162float(hb));
    lo = (uint32_t)__bfloat16_as_ushort(la) | ((uint32_t)__bfloat16_as_ushort(lb) << 16);
    return (uint32_t)__bfloat16_as_ushort(ha) | ((uint32_t)__bfloat16_as_ushort(hb) << 16);
}
__device__ __forceinline__ void ldsm4(uint32_t* r, uint32_t a) {
    asm volatile("ldmatrix.sync.aligned.m8n8.x4.shared.b16 {%0,%1,%2,%3}, [%4];"
        : "=r"(r[0]), "=r"(r[1]), "=r"(r[2]), "=r"(r[3]) : "r"(a));
}
__device__ __forceinline__ void ldsm4t(uint32_t* r, uint32_t a) {
    asm volatile("ldmatrix.sync.aligned.m8n8.x4.trans.shared.b16 {%0,%1,%2,%3}, [%4];"
        : "=r"(r[0]), "=r"(r[1]), "=r"(r[2]), "=r"(r[3]) : "r"(a));
}
__device__ __forceinline__ void mmab(float* d, const uint32_t* a, uint32_t b0, uint32_t b1) {
    asm("mma.sync.aligned.m16n8k16.row.col.f32.bf16.bf16.f32 "
        "{%0,%1,%2,%3}, {%4,%5,%6,%7}, {%8,%9}, {%0,%1,%2,%3};"
        : "+f"(d[0]), "+f"(d[1]), "+f"(d[2]), "+f"(d[3])
        : "r"(a[0]), "r"(a[1]), "r"(a[2]), "r"(a[3]), "r"(b0), "r"(b1));
}
// load rows row0.. (clamped) -> bf16 hi/lo smem; row stride 256B, chunk swz c^(r&7)
template <int ITERS>
__device__ __forceinline__ void ldcv(const float* __restrict__ src, int row0, int cap,
                                     char* smc, int Ho, int gap, int tid) {
    #pragma unroll
    for (int t = 0; t < ITERS; t++) {
        int idx = tid + t * NTHREADS;
        int r = idx >> 5, c4 = idx & 31;
        int gr = row0 + r; if (gr >= cap) gr = cap - 1;
        float4 v = *(const float4*)(src + (size_t)gr * DHEAD + (c4 << 2));
        uint32_t l0, l1;
        uint32_t h0 = packhl(v.x, v.y, l0);
        uint32_t h1 = packhl(v.z, v.w, l1);
        int byte = (r << 8) + ((((c4 >> 1) ^ (r & 7)) << 4) + ((c4 & 1) << 3));
        *(uint2*)(smc + Ho + byte)       = make_uint2(h0, h1);
        *(uint2*)(smc + Ho + gap + byte) = make_uint2(l0, l1);
    }
}

// ---------------------------------------------------------------------------
// HMMA attention, BM=128. 16 warps: wr=wid&7 (16 rows each), wc=wid>>3
// (32 S-cols / 64 O-cols). QK: S(128x64) bf16 hi/lo 3-pass; PV: O(128x128)
// likewise with ldmatrix.trans on natural [key][d] V.
// ---------------------------------------------------------------------------
__global__ __launch_bounds__(NTHREADS, 1)
void attn_kernel(const float* __restrict__ Q, const float* __restrict__ K,
                 const float* __restrict__ V, const int* __restrict__ bseg) {
    extern __shared__ char smc[];
    __shared__ int s_seg[NUMB + 1], s_iofs[NUMB + 1], s_work;
    __shared__ float Lx[2][128];

    const int tid = threadIdx.x;
    const int lane = tid & 31, wid = tid >> 5;
    const int wr = wid & 7, wc = wid >> 3;
    const int g = lane >> 2, qx = lane & 3;
    const int arow = (lane & 7) + ((lane >> 3) & 1) * 8;
    const int asel = lane >> 4, lx7 = lane & 7;
    const uint32_t smu = (uint32_t)__cvta_generic_to_shared(smc);
    const float isd = 0.0883883476483184f;

    // ---- per-CTA segment detection (replaces prep kernel) ----
    for (int i = tid; i < N_TOK; i += NTHREADS) {
        if (i == 0) { int c = bseg[0]; for (int b = 0; b <= c; b++) s_seg[b] = 0; }
        else { int a = bseg[i - 1], c = bseg[i];
               for (int b = a + 1; b <= c; b++) s_seg[b] = i; }
    }
    if (tid == 0) {
        int last = bseg[N_TOK - 1];
        for (int b = last + 1; b <= NUMB; b++) s_seg[b] = N_TOK;
    }
    __syncthreads();
    if (tid == 0) {
        int run = 0;
        for (int b = 0; b < NUMB; b++) {
            s_iofs[b] = run;
            int rows = s_seg[b + 1] - s_seg[b];
            run += ((rows + BM - 1) / BM) * ((rows + KSPLIT - 1) / KSPLIT);
        }
        s_iofs[NUMB] = run;
    }
    if (blockIdx.x == 0 && tid <= NUMB) g_seg_start[tid] = s_seg[tid];
    __syncthreads();
    const int nitems = s_iofs[NUMB];

    const uint32_t qbase = smu + QH_O + (uint32_t)(16 * wr + arow) * 256;
    const uint32_t kbase = smu + KH_O + (uint32_t)(32 * wc + arow) * 256;
    const uint32_t pbase = smu + PH_O + (uint32_t)(16 * wr + arow) * 128;

    while (true) {
        __syncthreads();
        if (tid == 0) s_work = atomicAdd(&g_ctr, 1);
        __syncthreads();
        const int w = s_work;
        if (w >= nitems) break;
        int b2 = 0; while (w >= s_iofs[b2 + 1]) b2++;
        int rel = w - s_iofs[b2];
        int lo = s_seg[b2], hi = s_seg[b2 + 1];
        int nkp = (hi - lo + KSPLIT - 1) / KSPLIT;
        int rt = rel / nkp;
        const int part = rel - rt * nkp;
        const int r0g = lo + rt * BM, nrows = min(BM, hi - r0g);
        const int klo = lo + part * KSPLIT, kend = min(klo + KSPLIT, hi);

        ldcv<8>(Q, r0g, r0g + nrows, smc, QH_O, Q_GAP, tid);   // Q (sync below)

        float o[8][4];
        #pragma unroll
        for (int t = 0; t < 8; t++)
            { o[t][0] = 0.f; o[t][1] = 0.f; o[t][2] = 0.f; o[t][3] = 0.f; }
        float lsg0 = 0.f, lsg1 = 0.f;

        for (int kt = klo; kt < kend; kt += BN) {
            __syncthreads();                       // prev PV done; Q ready (1st)
            ldcv<4>(K, kt, kend, smc, KH_O, KV_GAP, tid);
            __syncthreads();

            // ---- QK: 4 n8-tiles x 8 k16-chunks x 3 passes ----
            float cs[4][4];
            #pragma unroll
            for (int t = 0; t < 4; t++)
                { cs[t][0] = 0.f; cs[t][1] = 0.f; cs[t][2] = 0.f; cs[t][3] = 0.f; }
            #pragma unroll
            for (int kc = 0; kc < 8; kc++) {
                uint32_t co = (uint32_t)(((2 * kc + asel) ^ lx7) << 4);
                uint32_t ah[4], al[4], b0h[4], b1h[4], b0l[4], b1l[4];
                ldsm4(ah, qbase + co);
                ldsm4(al, qbase + Q_GAP + co);
                ldsm4(b0h, kbase + co);
                ldsm4(b1h, kbase + 4096 + co);
                ldsm4(b0l, kbase + KV_GAP + co);
                ldsm4(b1l, kbase + KV_GAP + 4096 + co);
                mmab(cs[0], ah, b0h[0], b0h[2]);
                mmab(cs[0], ah, b0l[0], b0l[2]);
                mmab(cs[0], al, b0h[0], b0h[2]);
                mmab(cs[1], ah, b0h[1], b0h[3]);
                mmab(cs[1], ah, b0l[1], b0l[3]);
                mmab(cs[1], al, b0h[1], b0h[3]);
                mmab(cs[2], ah, b1h[0], b1h[2]);
                mmab(cs[2], ah, b1l[0], b1l[2]);
                mmab(cs[2], al, b1h[0], b1h[2]);
                mmab(cs[3], ah, b1h[1], b1h[3]);
                mmab(cs[3], ah, b1l[1], b1l[3]);
                mmab(cs[3], al, b1h[1], b1h[3]);
            }

            // ---- exp + mask + P store (bf16 hi/lo) ----
            #pragma unroll
            for (int t = 0; t < 4; t++) {
                int nb = 32 * wc + 8 * t;
                int col0 = kt + nb + 2 * qx;
                float e0 = (col0     < kend) ? __expf(cs[t][0] * isd) : 0.f;
                float e1 = (col0 + 1 < kend) ? __expf(cs[t][1] * isd) : 0.f;
                float e2 = (col0     < kend) ? __expf(cs[t][2] * isd) : 0.f;
                float e3 = (col0 + 1 < kend) ? __expf(cs[t][3] * isd) : 0.f;
                lsg0 += e0 + e1; lsg1 += e2 + e3;
                int tc = nb >> 3;
                int rA = 16 * wr + g, rB = rA + 8;
                uint32_t pl0, pl1;
                uint32_t ph0 = packhl(e0, e1, pl0);
                uint32_t ph1 = packhl(e2, e3, pl1);
                uint32_t offA = (uint32_t)(rA * 128 + ((tc ^ (rA & 7)) << 4) + 4 * qx);
                uint32_t offB = (uint32_t)(rB * 128 + ((tc ^ (rB & 7)) << 4) + 4 * qx);
                *(uint32_t*)(smc + PH_O + offA) = ph0;
                *(uint32_t*)(smc + PH_O + P_GAP + offA) = pl0;
                *(uint32_t*)(smc + PH_O + offB) = ph1;
                *(uint32_t*)(smc + PH_O + P_GAP + offB) = pl1;
            }
            __syncthreads();                       // P visible; K reads done
            ldcv<4>(V, kt, kend, smc, VH_O, KV_GAP, tid);
            __syncthreads();

            // ---- PV: 8 n8-tiles x 4 k16-chunks x 3 passes ----
            #pragma unroll
            for (int kc = 0; kc < 4; kc++) {
                uint32_t co = (uint32_t)(((2 * kc + asel) ^ lx7) << 4);
                uint32_t pah[4], pal[4];
                ldsm4(pah, pbase + co);
                ldsm4(pal, pbase + P_GAP + co);
                uint32_t vb = smu + VH_O + (uint32_t)(16 * kc + arow) * 256;
                #pragma unroll
                for (int i = 0; i < 4; i++) {
                    uint32_t vo = (uint32_t)(((8 * wc + 2 * i + asel) ^ lx7) << 4);
                    uint32_t vh[4], vl[4];
                    ldsm4t(vh, vb + vo);
                    ldsm4t(vl, vb + KV_GAP + vo);
                    mmab(o[2 * i], pah, vh[0], vh[1]);
                    mmab(o[2 * i], pah, vl[0], vl[1]);
                    mmab(o[2 * i], pal, vh[0], vh[1]);
                    mmab(o[2 * i + 1], pah, vh[2], vh[3]);
                    mmab(o[2 * i + 1], pah, vl[2], vl[3]);
                    mmab(o[2 * i + 1], pal, vh[2], vh[3]);
                }
            }
        }

        // ---- epilogue ----
        float s0 = lsg0, s1 = lsg1;
        s0 += __shfl_xor_sync(0xffffffffu, s0, 1);
        s0 += __shfl_xor_sync(0xffffffffu, s0, 2);
        s1 += __shfl_xor_sync(0xffffffffu, s1, 1);
        s1 += __shfl_xor_sync(0xffffffffu, s1, 2);
        if (qx == 0) { Lx[wc][16 * wr + g] = s0; Lx[wc][16 * wr + g + 8] = s1; }
        int rA = 16 * wr + g, rB = rA + 8;
        if (rA < nrows) {
            float* dst = &g_pO[part][r0g + rA][64 * wc + 2 * qx];
            #pragma unroll
            for (int t = 0; t < 8; t++)
                *(float2*)(dst + 8 * t) = make_float2(o[t][0], o[t][1]);
        }
        if (rB < nrows) {
            float* dst = &g_pO[part][r0g + rB][64 * wc + 2 * qx];
            #pragma unroll
            for (int t = 0; t < 8; t++)
                *(float2*)(dst + 8 * t) = make_float2(o[t][2], o[t][3]);
        }
        __syncthreads();
        if (tid < 128 && tid < nrows)
            g_pl[part][r0g + tid] = Lx[0][tid] + Lx[1][tid];
    }
}

// ---------------------------------------------------------------------------
__global__ void combine_kernel(const int* __restrict__ bseg,
                               float* __restrict__ out) {
    int idx = blockIdx.x * blockDim.x + threadIdx.x;
    if (idx == 0) g_ctr = 0;                      // reset queue for next replay
    int r = idx >> 5, c4 = idx & 31;
    int b = bseg[r];
    int span = g_seg_start[b + 1] - g_seg_start[b];
    int np = (span + KSPLIT - 1) / KSPLIT;
    float4 a = *(const float4*)&g_pO[0][r][c4 * 4];
    float l = g_pl[0][r];
    for (int p = 1; p < np; p++) {
        float4 t = *(const float4*)&g_pO[p][r][c4 * 4];
        a.x += t.x; a.y += t.y; a.z += t.z; a.w += t.w;
        l += g_pl[p][r];
    }
    float inv = 1.0f / l;   // EPS negligible (validated R2-R16)
    a.x *= inv; a.y *= inv; a.z *= inv; a.w *= inv;
    *(float4*)&out[(size_t)r * DHEAD + c4 * 4] = a;
}

// ---------------------------------------------------------------------------
extern "C" void kernel_launch(void* const* d_in, const int* in_sizes, int n_in,
                              void* d_out, int out_size) {
    const float* Q  = (const float*)d_in[0];
    const float* K  = (const float*)d_in[1];
    const float* V  = (const float*)d_in[2];
    const int* bseg = (const int*)d_in[n_in - 1];
    float* out      = (float*)d_out;

    cudaFuncSetAttribute(attn_kernel, cudaFuncAttributeMaxDynamicSharedMemorySize,
                         SMEMB);
    attn_kernel<<<NWORKERS, NTHREADS, SMEMB>>>(Q, K, V, bseg);
    combine_kernel<<<N_TOK * 32 / 256, 256>>>(bseg, out);
}